// round 1
// baseline (speedup 1.0000x reference)
#include <cuda_runtime.h>
#include <math.h>

#define NCHK 256
#define BSZ 32
#define NROWS (BSZ * NCHK * 16)   // 131072 rows of the flattened problem

// ---------------- scratch (static device globals; no allocation) -------------
__device__ int   g_is64;
__device__ float g_watch[NROWS * 16];  // [row][16]   row = (b*NCHK+t)*16+r
__device__ float g_A[NROWS * 64];      // [(b*16+r)*NCHK + t][64]  (= watch@Ws_top + bs)
__device__ float g_sus[NROWS * 64];    // [row][64]   sus entering chunk t

// ---------------- packed f32x2 helpers ---------------------------------------
__device__ __forceinline__ unsigned long long pk2(float lo, float hi) {
    unsigned long long r;
    asm("mov.b64 %0, {%1,%2};" : "=l"(r) : "f"(lo), "f"(hi));
    return r;
}
__device__ __forceinline__ void upk2(unsigned long long v, float& lo, float& hi) {
    asm("mov.b64 {%0,%1}, %2;" : "=f"(lo), "=f"(hi) : "l"(v));
}
__device__ __forceinline__ unsigned long long fma2(unsigned long long a,
                                                   unsigned long long b,
                                                   unsigned long long c) {
    unsigned long long d;
    asm("fma.rn.f32x2 %0, %1, %2, %3;" : "=l"(d) : "l"(a), "l"(b), "l"(c));
    return d;
}

// ---------------- kernel 0: detect int32 vs int64 token ids ------------------
__global__ void k_detect(const unsigned int* __restrict__ x) {
    // If x is int64 (values < 2^31, nonnegative), every odd 32-bit word is 0.
    unsigned int v = x[threadIdx.x * 2 + 1];
    unsigned int any = __ballot_sync(0xffffffffu, v != 0u);
    if (threadIdx.x == 0) g_is64 = (any == 0u) ? 1 : 0;
}

// ---------------- Phase A: attention + LN + A = watch@Ws_top + bs ------------
__global__ __launch_bounds__(256) void k_phaseA(
    const void* __restrict__ xraw, const float* __restrict__ emb,
    const float* __restrict__ Wq, const float* __restrict__ bq,
    const float* __restrict__ Wk, const float* __restrict__ bk,
    const float* __restrict__ Wv, const float* __restrict__ bv,
    const float* __restrict__ glim, const float* __restrict__ blim,
    const float* __restrict__ Ws, const float* __restrict__ bs)
{
    int bt = blockIdx.x;                 // b*NCHK + t
    int tid = threadIdx.x;
    int i = tid >> 4, j = tid & 15;

    __shared__ float rd[16][17], qs[16][17], ks[16][17], vs[16][17];
    __shared__ float es[16][17], ps[16][17], wls[16][17];
    __shared__ float wq_s[256], wk_s[256], wv_s[256];

    wq_s[tid] = Wq[tid];
    wk_s[tid] = Wk[tid];
    wv_s[tid] = Wv[tid];

    long long id;
    int xbase = bt * 16 + i;             // = b*4096 + t*16 + i
    if (g_is64) id = ((const long long*)xraw)[xbase];
    else        id = (long long)((const int*)xraw)[xbase];
    rd[i][j] = emb[(int)id * 16 + j];
    __syncthreads();

    float aq = bq[j], ak = bk[j], av = bv[j];
    #pragma unroll
    for (int d = 0; d < 16; d++) {
        float r = rd[i][d];
        aq = fmaf(r, wq_s[d * 16 + j], aq);
        ak = fmaf(r, wk_s[d * 16 + j], ak);
        av = fmaf(r, wv_s[d * 16 + j], av);
    }
    qs[i][j] = aq; ks[i][j] = ak; vs[i][j] = av;
    __syncthreads();

    float sc = 0.f;
    #pragma unroll
    for (int d = 0; d < 16; d++) sc = fmaf(qs[i][d], ks[j][d], sc);
    sc *= 0.25f;                         // 1/sqrt(16)
    es[i][j] = sc;
    __syncthreads();

    float mx = -1e30f;
    #pragma unroll
    for (int d = 0; d < 16; d++) mx = fmaxf(mx, es[i][d]);
    float e = expf(sc - mx);
    ps[i][j] = e;
    __syncthreads();

    float sm = 0.f;
    #pragma unroll
    for (int d = 0; d < 16; d++) sm += ps[i][d];
    float p = e / sm;
    es[i][j] = p;                        // safe: all mx reads happened before prev sync
    __syncthreads();

    float w = 0.f;
    #pragma unroll
    for (int d = 0; d < 16; d++) w = fmaf(es[i][d], vs[d][j], w);
    wls[i][j] = w;
    __syncthreads();

    float mean = 0.f;
    #pragma unroll
    for (int d = 0; d < 16; d++) mean += wls[i][d];
    mean *= 0.0625f;
    float var = 0.f;
    #pragma unroll
    for (int d = 0; d < 16; d++) { float dd = wls[i][d] - mean; var = fmaf(dd, dd, var); }
    var *= 0.0625f;
    float wl = (w - mean) * rsqrtf(var + 1e-5f) * glim[j] + blim[j];

    g_watch[(bt * 16 + i) * 16 + j] = wl;
    ps[i][j] = wl;                       // reuse ps for LN'd watch
    __syncthreads();

    int b = bt >> 8, t = bt & 255;
    int abase = ((b * 16 + i) * NCHK + t) * 64;
    #pragma unroll
    for (int cc = 0; cc < 4; cc++) {
        int c = j + cc * 16;
        float a = bs[c];
        #pragma unroll
        for (int d = 0; d < 16; d++) a = fmaf(ps[i][d], Ws[d * 64 + c], a);
        g_A[abase + c] = a;
    }
}

// ---------------- Phase B: 512 independent 256-step recurrences --------------
__global__ __launch_bounds__(64) void k_phaseB(
    const float* __restrict__ Ws,
    const float* __restrict__ gdb, const float* __restrict__ bdb)
{
    int br = blockIdx.x;                 // b*16 + r
    int j = threadIdx.x;                 // 0..63
    __shared__ float ssh[64];
    __shared__ float red[4];

    float wcol[64];
    #pragma unroll
    for (int i = 0; i < 64; i++) wcol[i] = Ws[(16 + i) * 64 + j];
    float gd = gdb[j], bdj = bdb[j];

    float sj = 0.0f;
    ssh[j] = 0.0f;
    __syncthreads();

    const float* Arow = g_A + (size_t)br * (NCHK * 64);
    float apre = Arow[j];
    int lane = j & 31, warp = j >> 5;
    float* susp = g_sus + (size_t)(br >> 4) * (NCHK * 16 * 64) + (size_t)(br & 15) * 64;

    for (int t = 0; t < NCHK; t++) {
        susp[(size_t)t * 1024 + j] = sj;           // sus ENTERING chunk t
        float h = apre;
        if (t + 1 < NCHK) apre = Arow[(t + 1) * 64 + j];
        #pragma unroll
        for (int i = 0; i < 64; i++) h = fmaf(ssh[i], wcol[i], h);
        float g = 0.5f * h * (1.0f + erff(h * 0.70710678118654752f));  // exact gelu
        float s1 = g, s2 = g * g;
        #pragma unroll
        for (int o = 16; o; o >>= 1) {
            s1 += __shfl_xor_sync(0xffffffffu, s1, o);
            s2 += __shfl_xor_sync(0xffffffffu, s2, o);
        }
        if (lane == 0) { red[warp * 2] = s1; red[warp * 2 + 1] = s2; }
        __syncthreads();
        float mean = (red[0] + red[2]) * (1.0f / 64.0f);
        float ex2  = (red[1] + red[3]) * (1.0f / 64.0f);
        float var = fmaxf(ex2 - mean * mean, 0.0f);
        sj = (g - mean) * rsqrtf(var + 1e-5f) * gd + bdj;
        ssh[j] = sj;
        __syncthreads();
    }
}

// ---------------- Phase C: [131072,80] @ [80,512] + row-LN, f32x2 ------------
#define SMEMC_WD    (80 * 512 * 4)       // 163840
#define SMEMC_STAGE (80 * 64 * 8)        // 40960
#define SMEMC_RED   (16 * 16 * 4)        // 1024
#define SMEMC_BYTES (SMEMC_WD + SMEMC_STAGE + SMEMC_RED)

__global__ __launch_bounds__(512, 1) void k_phaseC(
    const float* __restrict__ Wd, const float* __restrict__ bd,
    const float* __restrict__ gch, const float* __restrict__ bch,
    float* __restrict__ out)
{
    extern __shared__ char smc[];
    float* wd_sh = (float*)smc;                                    // [80][512]
    unsigned long long* stage = (unsigned long long*)(smc + SMEMC_WD); // [80][64] dup-pairs
    float* red = (float*)(smc + SMEMC_WD + SMEMC_STAGE);           // [16 warps][8 rows][2]

    int tid = threadIdx.x;
    int ct = tid & 63;                   // column-thread: cols ct*8 .. ct*8+7
    int rg = tid >> 6;                   // row-group: rows rg*8 .. rg*8+7
    int lane = tid & 31, warpid = tid >> 5;

    // preload Wd into shared (float4)
    {
        const float4* wd4 = (const float4*)Wd;
        float4* wds4 = (float4*)wd_sh;
        #pragma unroll
        for (int k = 0; k < 20; k++) wds4[tid + k * 512] = wd4[tid + k * 512];
    }
    unsigned long long bdp[4];
    {
        const unsigned long long* bd64 = (const unsigned long long*)bd;
        #pragma unroll
        for (int p = 0; p < 4; p++) bdp[p] = __ldg(&bd64[ct * 4 + p]);
    }

    for (int tile = blockIdx.x; tile < NROWS / 64; tile += gridDim.x) {
        int rowbase = tile * 64;
        // stage 64 rows x 80 values, duplicated into f32x2 pairs, layout [c][row]
        for (int idx = tid; idx < 80 * 64; idx += 512) {
            int c = idx >> 6;
            int rr = idx & 63;
            int grow = rowbase + rr;
            float v = (c < 16) ? g_watch[grow * 16 + c]
                               : g_sus[(size_t)grow * 64 + (c - 16)];
            stage[idx] = pk2(v, v);
        }
        __syncthreads();

        unsigned long long acc[8][4];
        #pragma unroll
        for (int r = 0; r < 8; r++)
            #pragma unroll
            for (int p = 0; p < 4; p++) acc[r][p] = bdp[p];

        const unsigned long long* sp = stage + (rg << 3);
        const float* wp = wd_sh + (ct << 3);
        #pragma unroll 4
        for (int i = 0; i < 80; i++) {
            longlong2 rA = *(const longlong2*)(sp);
            longlong2 rB = *(const longlong2*)(sp + 2);
            longlong2 rC = *(const longlong2*)(sp + 4);
            longlong2 rD = *(const longlong2*)(sp + 6);
            longlong2 wA = *(const longlong2*)(wp);
            longlong2 wB = *(const longlong2*)(wp + 4);
            unsigned long long rv[8] = {
                (unsigned long long)rA.x, (unsigned long long)rA.y,
                (unsigned long long)rB.x, (unsigned long long)rB.y,
                (unsigned long long)rC.x, (unsigned long long)rC.y,
                (unsigned long long)rD.x, (unsigned long long)rD.y };
            unsigned long long wv[4] = {
                (unsigned long long)wA.x, (unsigned long long)wA.y,
                (unsigned long long)wB.x, (unsigned long long)wB.y };
            #pragma unroll
            for (int r = 0; r < 8; r++)
                #pragma unroll
                for (int p = 0; p < 4; p++)
                    acc[r][p] = fma2(rv[r], wv[p], acc[r][p]);
            sp += 64; wp += 512;
        }

        // row LN over 512 cols (each row owned by 2 warps = 64 col-threads)
        #pragma unroll
        for (int r = 0; r < 8; r++) {
            float s1 = 0.f, s2 = 0.f;
            #pragma unroll
            for (int p = 0; p < 4; p++) {
                float lo, hi; upk2(acc[r][p], lo, hi);
                s1 += lo + hi;
                s2 = fmaf(lo, lo, s2); s2 = fmaf(hi, hi, s2);
            }
            #pragma unroll
            for (int o = 16; o; o >>= 1) {
                s1 += __shfl_xor_sync(0xffffffffu, s1, o);
                s2 += __shfl_xor_sync(0xffffffffu, s2, o);
            }
            if (lane == 0) {
                red[warpid * 16 + r * 2]     = s1;
                red[warpid * 16 + r * 2 + 1] = s2;
            }
        }
        __syncthreads();

        float gcv[8], bcv[8];
        {
            const float4* g4 = (const float4*)gch;
            const float4* b4 = (const float4*)bch;
            float4 a = g4[ct * 2], b2 = g4[ct * 2 + 1];
            gcv[0]=a.x; gcv[1]=a.y; gcv[2]=a.z; gcv[3]=a.w;
            gcv[4]=b2.x; gcv[5]=b2.y; gcv[6]=b2.z; gcv[7]=b2.w;
            float4 c = b4[ct * 2], d2 = b4[ct * 2 + 1];
            bcv[0]=c.x; bcv[1]=c.y; bcv[2]=c.z; bcv[3]=c.w;
            bcv[4]=d2.x; bcv[5]=d2.y; bcv[6]=d2.z; bcv[7]=d2.w;
        }

        int w0 = (rg * 2) * 16, w1 = (rg * 2 + 1) * 16;
        #pragma unroll
        for (int r = 0; r < 8; r++) {
            float s1 = red[w0 + r * 2]     + red[w1 + r * 2];
            float s2 = red[w0 + r * 2 + 1] + red[w1 + r * 2 + 1];
            float mean = s1 * (1.0f / 512.0f);
            float var  = fmaxf(s2 * (1.0f / 512.0f) - mean * mean, 0.0f);
            float inv  = rsqrtf(var + 1e-5f);
            float o[8];
            #pragma unroll
            for (int p = 0; p < 4; p++) {
                float lo, hi; upk2(acc[r][p], lo, hi);
                o[2*p]   = (lo - mean) * inv * gcv[2*p]   + bcv[2*p];
                o[2*p+1] = (hi - mean) * inv * gcv[2*p+1] + bcv[2*p+1];
            }
            float4* outp = (float4*)(out + (size_t)(rowbase + rg * 8 + r) * 512 + ct * 8);
            outp[0] = make_float4(o[0], o[1], o[2], o[3]);
            outp[1] = make_float4(o[4], o[5], o[6], o[7]);
        }
        __syncthreads();   // before next tile overwrites stage/red
    }
}

// ---------------- launcher ----------------------------------------------------
extern "C" void kernel_launch(void* const* d_in, const int* in_sizes, int n_in,
                              void* d_out, int out_size) {
    const void*  x     = d_in[0];
    const float* emb   = (const float*)d_in[1];
    const float* Wq    = (const float*)d_in[2];
    const float* bq    = (const float*)d_in[3];
    const float* Wk    = (const float*)d_in[4];
    const float* bk    = (const float*)d_in[5];
    const float* Wv    = (const float*)d_in[6];
    const float* bv    = (const float*)d_in[7];
    const float* glim  = (const float*)d_in[8];
    const float* blim  = (const float*)d_in[9];
    const float* Ws    = (const float*)d_in[10];
    const float* bs    = (const float*)d_in[11];
    const float* gdb   = (const float*)d_in[12];
    const float* bdb   = (const float*)d_in[13];
    const float* Wd    = (const float*)d_in[14];
    const float* bd    = (const float*)d_in[15];
    const float* gch   = (const float*)d_in[16];
    const float* bch   = (const float*)d_in[17];
    float* out = (float*)d_out;

    cudaFuncSetAttribute(k_phaseC, cudaFuncAttributeMaxDynamicSharedMemorySize,
                         SMEMC_BYTES);

    k_detect<<<1, 32>>>((const unsigned int*)x);
    k_phaseA<<<BSZ * NCHK, 256>>>(x, emb, Wq, bq, Wk, bk, Wv, bv,
                                  glim, blim, Ws, bs);
    k_phaseB<<<BSZ * 16, 64>>>(Ws, gdb, bdb);
    k_phaseC<<<152, 512, SMEMC_BYTES>>>(Wd, bd, gch, bch, out);
}

// round 2
// speedup vs baseline: 1.4720x; 1.4720x over previous
#include <cuda_runtime.h>
#include <cuda_bf16.h>
#include <math.h>

#define NCHK 256
#define BSZ 32
#define NROWS (BSZ * NCHK * 16)   // 131072 rows of the flattened GEMM

// ---------------- scratch (static device globals; no allocation) -------------
__device__ int   g_is64;
__device__ float g_watch[NROWS * 16];  // [row][16]
__device__ float g_A[NROWS * 64];      // [(b*16+r)*NCHK + t][64]
__device__ float g_sus[NROWS * 64];    // [row][64]
__device__ uint4 g_Bfrag[5 * 64 * 32]; // Wd in mma-fragment order (hi,hi,lo,lo)

// ---------------- bf16 split helpers -----------------------------------------
__device__ __forceinline__ void split2(float a, float b, unsigned& hi, unsigned& lo) {
    __nv_bfloat16 ha = __float2bfloat16_rn(a), hb = __float2bfloat16_rn(b);
    float ra = a - __bfloat162float(ha);
    float rb = b - __bfloat162float(hb);
    __nv_bfloat16 la = __float2bfloat16_rn(ra), lb = __float2bfloat16_rn(rb);
    hi = (unsigned)__bfloat16_as_ushort(ha) | ((unsigned)__bfloat16_as_ushort(hb) << 16);
    lo = (unsigned)__bfloat16_as_ushort(la) | ((unsigned)__bfloat16_as_ushort(lb) << 16);
}

__device__ __forceinline__ void mma16816(float* d,
                                         unsigned a0, unsigned a1, unsigned a2, unsigned a3,
                                         unsigned b0, unsigned b1) {
    asm volatile(
        "mma.sync.aligned.m16n8k16.row.col.f32.bf16.bf16.f32 "
        "{%0,%1,%2,%3}, {%4,%5,%6,%7}, {%8,%9}, {%0,%1,%2,%3};"
        : "+f"(d[0]), "+f"(d[1]), "+f"(d[2]), "+f"(d[3])
        : "r"(a0), "r"(a1), "r"(a2), "r"(a3), "r"(b0), "r"(b1));
}

// ---------------- kernel 0: detect int32 vs int64 token ids ------------------
__global__ void k_detect(const unsigned int* __restrict__ x) {
    unsigned int v = x[threadIdx.x * 2 + 1];
    unsigned int any = __ballot_sync(0xffffffffu, v != 0u);
    if (threadIdx.x == 0) g_is64 = (any == 0u) ? 1 : 0;
}

// ---------------- kernel: pre-split Wd into fragment-ordered hi/lo bf16 ------
__global__ void k_prepB(const float* __restrict__ Wd) {
    int w = blockIdx.x * blockDim.x + threadIdx.x;   // 0..10239
    if (w >= 5 * 64 * 32) return;
    int lane = w & 31;
    int ntg  = (w >> 5) & 63;
    int ks   = w >> 11;
    int g = lane >> 2, tig = lane & 3;
    int n  = ntg * 8 + g;
    int k0 = ks * 16 + tig * 2;
    float w00 = Wd[k0 * 512 + n],       w01 = Wd[(k0 + 1) * 512 + n];
    float w10 = Wd[(k0 + 8) * 512 + n], w11 = Wd[(k0 + 9) * 512 + n];
    unsigned bh0, bl0, bh1, bl1;
    split2(w00, w01, bh0, bl0);
    split2(w10, w11, bh1, bl1);
    g_Bfrag[w] = make_uint4(bh0, bh1, bl0, bl1);
}

// ---------------- Phase A: attention + LN + A = watch@Ws_top + bs ------------
__global__ __launch_bounds__(256) void k_phaseA(
    const void* __restrict__ xraw, const float* __restrict__ emb,
    const float* __restrict__ Wq, const float* __restrict__ bq,
    const float* __restrict__ Wk, const float* __restrict__ bk,
    const float* __restrict__ Wv, const float* __restrict__ bv,
    const float* __restrict__ glim, const float* __restrict__ blim,
    const float* __restrict__ Ws, const float* __restrict__ bs)
{
    int bt = blockIdx.x;
    int tid = threadIdx.x;
    int i = tid >> 4, j = tid & 15;

    __shared__ float rd[16][17], qs[16][17], ks[16][17], vs[16][17];
    __shared__ float es[16][17], ps[16][17], wls[16][17];
    __shared__ float wq_s[256], wk_s[256], wv_s[256];

    wq_s[tid] = Wq[tid];
    wk_s[tid] = Wk[tid];
    wv_s[tid] = Wv[tid];

    long long id;
    int xbase = bt * 16 + i;
    if (g_is64) id = ((const long long*)xraw)[xbase];
    else        id = (long long)((const int*)xraw)[xbase];
    rd[i][j] = emb[(int)id * 16 + j];
    __syncthreads();

    float aq = bq[j], ak = bk[j], av = bv[j];
    #pragma unroll
    for (int d = 0; d < 16; d++) {
        float r = rd[i][d];
        aq = fmaf(r, wq_s[d * 16 + j], aq);
        ak = fmaf(r, wk_s[d * 16 + j], ak);
        av = fmaf(r, wv_s[d * 16 + j], av);
    }
    qs[i][j] = aq; ks[i][j] = ak; vs[i][j] = av;
    __syncthreads();

    float sc = 0.f;
    #pragma unroll
    for (int d = 0; d < 16; d++) sc = fmaf(qs[i][d], ks[j][d], sc);
    sc *= 0.25f;
    es[i][j] = sc;
    __syncthreads();

    float mx = -1e30f;
    #pragma unroll
    for (int d = 0; d < 16; d++) mx = fmaxf(mx, es[i][d]);
    float e = __expf(sc - mx);
    ps[i][j] = e;
    __syncthreads();

    float sm = 0.f;
    #pragma unroll
    for (int d = 0; d < 16; d++) sm += ps[i][d];
    float p = e / sm;
    es[i][j] = p;
    __syncthreads();

    float w = 0.f;
    #pragma unroll
    for (int d = 0; d < 16; d++) w = fmaf(es[i][d], vs[d][j], w);
    wls[i][j] = w;
    __syncthreads();

    float mean = 0.f;
    #pragma unroll
    for (int d = 0; d < 16; d++) mean += wls[i][d];
    mean *= 0.0625f;
    float var = 0.f;
    #pragma unroll
    for (int d = 0; d < 16; d++) { float dd = wls[i][d] - mean; var = fmaf(dd, dd, var); }
    var *= 0.0625f;
    float wl = (w - mean) * rsqrtf(var + 1e-5f) * glim[j] + blim[j];

    g_watch[(bt * 16 + i) * 16 + j] = wl;
    ps[i][j] = wl;
    __syncthreads();

    int b = bt >> 8, t = bt & 255;
    int abase = ((b * 16 + i) * NCHK + t) * 64;
    #pragma unroll
    for (int cc = 0; cc < 4; cc++) {
        int c = j + cc * 16;
        float a = bs[c];
        #pragma unroll
        for (int d = 0; d < 16; d++) a = fmaf(ps[i][d], Ws[d * 64 + c], a);
        g_A[abase + c] = a;
    }
}

// ---------------- Phase B: 512 independent 256-step recurrences --------------
__global__ __launch_bounds__(64) void k_phaseB(
    const float* __restrict__ Ws,
    const float* __restrict__ gdb, const float* __restrict__ bdb)
{
    int br = blockIdx.x;
    int j = threadIdx.x;
    __shared__ float ssh[64];
    __shared__ float red[4];

    float wcol[64];
    #pragma unroll
    for (int i = 0; i < 64; i++) wcol[i] = Ws[(16 + i) * 64 + j];
    float gd = gdb[j], bdj = bdb[j];

    float sj = 0.0f;
    ssh[j] = 0.0f;
    __syncthreads();

    const float* Arow = g_A + (size_t)br * (NCHK * 64);
    float apre = Arow[j];
    int lane = j & 31, warp = j >> 5;
    float* susp = g_sus + (size_t)(br >> 4) * (NCHK * 16 * 64) + (size_t)(br & 15) * 64;

    for (int t = 0; t < NCHK; t++) {
        susp[(size_t)t * 1024 + j] = sj;
        float h0 = apre, h1 = 0.f, h2 = 0.f, h3 = 0.f;
        if (t + 1 < NCHK) apre = Arow[(t + 1) * 64 + j];
        #pragma unroll
        for (int i = 0; i < 64; i += 4) {
            h0 = fmaf(ssh[i],     wcol[i],     h0);
            h1 = fmaf(ssh[i + 1], wcol[i + 1], h1);
            h2 = fmaf(ssh[i + 2], wcol[i + 2], h2);
            h3 = fmaf(ssh[i + 3], wcol[i + 3], h3);
        }
        float h = (h0 + h1) + (h2 + h3);
        float g = 0.5f * h * (1.0f + erff(h * 0.70710678118654752f));
        float s1 = g, s2 = g * g;
        #pragma unroll
        for (int o = 16; o; o >>= 1) {
            s1 += __shfl_xor_sync(0xffffffffu, s1, o);
            s2 += __shfl_xor_sync(0xffffffffu, s2, o);
        }
        if (lane == 0) { red[warp * 2] = s1; red[warp * 2 + 1] = s2; }
        __syncthreads();
        float mean = (red[0] + red[2]) * (1.0f / 64.0f);
        float ex2  = (red[1] + red[3]) * (1.0f / 64.0f);
        float var = fmaxf(ex2 - mean * mean, 0.0f);
        sj = (g - mean) * rsqrtf(var + 1e-5f) * gd + bdj;
        ssh[j] = sj;
        __syncthreads();
    }
}

// ---------------- Phase C: tensor-core GEMM [131072,80]x[80,512] + row LN ----
#define C_SMEM_B    (5 * 64 * 32 * 16)   // 163840
#define C_SMEM_A    (5 * 4 * 32 * 16)    // 10240 per plane
#define C_SMEM_RED  4096
#define C_SMEM_VEC  (3 * 2048)
#define C_SMEM_BYTES (C_SMEM_B + 2 * C_SMEM_A + C_SMEM_RED + C_SMEM_VEC)

__global__ __launch_bounds__(512, 1) void k_phaseC(
    const float* __restrict__ bd, const float* __restrict__ gch,
    const float* __restrict__ bch, float* __restrict__ out)
{
    extern __shared__ char sm[];
    uint4*  sB   = (uint4*)sm;                                   // [5][64][32]
    unsigned* sAh = (unsigned*)(sm + C_SMEM_B);                  // [5][4][32][4]
    unsigned* sAl = (unsigned*)(sm + C_SMEM_B + C_SMEM_A);
    float2* sRed = (float2*)(sm + C_SMEM_B + 2 * C_SMEM_A);      // [64][8]
    float*  sG   = (float*)(sm + C_SMEM_B + 2 * C_SMEM_A + C_SMEM_RED);
    float*  sBc  = sG + 512;
    float*  sBd  = sBc + 512;

    int tid = threadIdx.x;
    int lane = tid & 31, warp = tid >> 5;
    int mw = warp & 1, nw = warp >> 1;        // 2 m-warps x 8 n-warps
    int g = lane >> 2, tig = lane & 3;

    for (int i = tid; i < 5 * 64 * 32; i += 512) sB[i] = g_Bfrag[i];
    if (tid < 512) { sG[tid] = gch[tid]; sBc[tid] = bch[tid]; sBd[tid] = bd[tid]; }
    __syncthreads();

    for (int tile = blockIdx.x; tile < NROWS / 64; tile += gridDim.x) {
        int rowbase = tile * 64;

        // ---- stage A (64 rows x 80 k) into fragment-ordered hi/lo bf16 ----
        for (int e = tid; e < 64 * 40; e += 512) {
            int m = e / 40, kp = e % 40;
            int k = kp * 2;
            int grow = rowbase + m;
            float2 v;
            if (k < 16) v = ((const float2*)g_watch)[grow * 8 + (k >> 1)];
            else        v = ((const float2*)g_sus)[(size_t)grow * 32 + ((k - 16) >> 1)];
            unsigned hi, lo; split2(v.x, v.y, hi, lo);
            int ks = k >> 4, kk = k & 15;
            int mt = m >> 4;
            int reg = ((kk >> 3) << 1) | ((m >> 3) & 1);
            int ln  = ((m & 7) << 2) | ((kk >> 1) & 3);
            int base = ((ks * 4 + mt) * 32 + ln) * 4 + reg;
            sAh[base] = hi;
            sAl[base] = lo;
        }
        __syncthreads();

        // ---- mma main loop ----
        float acc[2][8][4];
        #pragma unroll
        for (int nt = 0; nt < 8; nt++) {
            float2 b2 = *(const float2*)&sBd[nw * 64 + nt * 8 + tig * 2];
            #pragma unroll
            for (int mt = 0; mt < 2; mt++) {
                acc[mt][nt][0] = b2.x; acc[mt][nt][1] = b2.y;
                acc[mt][nt][2] = b2.x; acc[mt][nt][3] = b2.y;
            }
        }
        #pragma unroll
        for (int ks = 0; ks < 5; ks++) {
            uint4 aH0 = ((const uint4*)sAh)[(ks * 4 + mw * 2 + 0) * 32 + lane];
            uint4 aH1 = ((const uint4*)sAh)[(ks * 4 + mw * 2 + 1) * 32 + lane];
            uint4 aL0 = ((const uint4*)sAl)[(ks * 4 + mw * 2 + 0) * 32 + lane];
            uint4 aL1 = ((const uint4*)sAl)[(ks * 4 + mw * 2 + 1) * 32 + lane];
            #pragma unroll
            for (int nt = 0; nt < 8; nt++) {
                uint4 b = sB[(ks * 64 + nw * 8 + nt) * 32 + lane];
                mma16816(acc[0][nt], aH0.x, aH0.y, aH0.z, aH0.w, b.x, b.y);
                mma16816(acc[1][nt], aH1.x, aH1.y, aH1.z, aH1.w, b.x, b.y);
                mma16816(acc[0][nt], aH0.x, aH0.y, aH0.z, aH0.w, b.z, b.w);
                mma16816(acc[1][nt], aH1.x, aH1.y, aH1.z, aH1.w, b.z, b.w);
                mma16816(acc[0][nt], aL0.x, aL0.y, aL0.z, aL0.w, b.x, b.y);
                mma16816(acc[1][nt], aL1.x, aL1.y, aL1.z, aL1.w, b.x, b.y);
            }
        }

        // ---- epilogue: per-row LN over 512 cols ----
        float s1v[2][2], s2v[2][2];
        #pragma unroll
        for (int mt = 0; mt < 2; mt++)
            #pragma unroll
            for (int rh = 0; rh < 2; rh++) {
                float s1 = 0.f, s2 = 0.f;
                #pragma unroll
                for (int nt = 0; nt < 8; nt++) {
                    float x = acc[mt][nt][rh * 2], y = acc[mt][nt][rh * 2 + 1];
                    s1 += x + y;
                    s2 = fmaf(x, x, s2); s2 = fmaf(y, y, s2);
                }
                s1 += __shfl_xor_sync(0xffffffffu, s1, 1);
                s2 += __shfl_xor_sync(0xffffffffu, s2, 1);
                s1 += __shfl_xor_sync(0xffffffffu, s1, 2);
                s2 += __shfl_xor_sync(0xffffffffu, s2, 2);
                s1v[mt][rh] = s1; s2v[mt][rh] = s2;
            }
        if (tig == 0) {
            #pragma unroll
            for (int mt = 0; mt < 2; mt++)
                #pragma unroll
                for (int rh = 0; rh < 2; rh++) {
                    int m = mw * 32 + mt * 16 + rh * 8 + g;
                    sRed[m * 8 + nw] = make_float2(s1v[mt][rh], s2v[mt][rh]);
                }
        }
        __syncthreads();

        #pragma unroll
        for (int mt = 0; mt < 2; mt++)
            #pragma unroll
            for (int rh = 0; rh < 2; rh++) {
                int m = mw * 32 + mt * 16 + rh * 8 + g;
                float t1 = 0.f, t2 = 0.f;
                #pragma unroll
                for (int w8 = 0; w8 < 8; w8++) {
                    float2 p = sRed[m * 8 + w8];
                    t1 += p.x; t2 += p.y;
                }
                float mean = t1 * (1.0f / 512.0f);
                float var  = fmaxf(t2 * (1.0f / 512.0f) - mean * mean, 0.0f);
                float inv  = rsqrtf(var + 1e-5f);
                size_t grow = (size_t)(rowbase + m);
                #pragma unroll
                for (int nt = 0; nt < 8; nt++) {
                    int c = nw * 64 + nt * 8 + tig * 2;
                    float2 gg = *(const float2*)&sG[c];
                    float2 bb = *(const float2*)&sBc[c];
                    float x = acc[mt][nt][rh * 2], y = acc[mt][nt][rh * 2 + 1];
                    float2 o;
                    o.x = (x - mean) * inv * gg.x + bb.x;
                    o.y = (y - mean) * inv * gg.y + bb.y;
                    *(float2*)&out[grow * 512 + c] = o;
                }
            }
        __syncthreads();   // protect sRed/sA before next tile
    }
}

// ---------------- launcher ----------------------------------------------------
extern "C" void kernel_launch(void* const* d_in, const int* in_sizes, int n_in,
                              void* d_out, int out_size) {
    const void*  x     = d_in[0];
    const float* emb   = (const float*)d_in[1];
    const float* Wq    = (const float*)d_in[2];
    const float* bq    = (const float*)d_in[3];
    const float* Wk    = (const float*)d_in[4];
    const float* bk    = (const float*)d_in[5];
    const float* Wv    = (const float*)d_in[6];
    const float* bv    = (const float*)d_in[7];
    const float* glim  = (const float*)d_in[8];
    const float* blim  = (const float*)d_in[9];
    const float* Ws    = (const float*)d_in[10];
    const float* bs    = (const float*)d_in[11];
    const float* gdb   = (const float*)d_in[12];
    const float* bdb   = (const float*)d_in[13];
    const float* Wd    = (const float*)d_in[14];
    const float* bd    = (const float*)d_in[15];
    const float* gch   = (const float*)d_in[16];
    const float* bch   = (const float*)d_in[17];
    float* out = (float*)d_out;

    cudaFuncSetAttribute(k_phaseC, cudaFuncAttributeMaxDynamicSharedMemorySize,
                         C_SMEM_BYTES);

    k_detect<<<1, 32>>>((const unsigned int*)x);
    k_prepB<<<40, 256>>>(Wd);
    k_phaseA<<<BSZ * NCHK, 256>>>(x, emb, Wq, bq, Wk, bk, Wv, bv,
                                  glim, blim, Ws, bs);
    k_phaseB<<<BSZ * 16, 64>>>(Ws, gdb, bdb);
    k_phaseC<<<152, 512, C_SMEM_BYTES>>>(bd, gch, bch, out);
}